// round 11
// baseline (speedup 1.0000x reference)
#include <cuda_runtime.h>
#include <math.h>

#define HH 512
#define WW 512
#define NB 8
#define NIMG 16
#define FULL 0xffffffffu
#define K1BLK 512
#define K1THR 256
#define K2BLK 512
#define K2THR 256

// packed thresholded masks: [image][row][16 words of 32 cols] = 512 KB
__device__ unsigned int g_mbits[NIMG][HH][16];
// per-(image, block) nonempty flags (overwritten every replay)
__device__ int g_anyp[NIMG][32];
// running max dt^2 per EDT-image; reset by finalizer each replay
__device__ unsigned int g_hmax[NIMG];
// last-arriver counter (monotonic across replays)
__device__ unsigned int g_done = 0;

__device__ __forceinline__ unsigned nib4(float4 v) {
    return (v.x > 0.5f ? 1u : 0u) | (v.y > 0.5f ? 2u : 0u)
         | (v.z > 0.5f ? 4u : 0u) | (v.w > 0.5f ? 8u : 0u);
}
__device__ __forceinline__ unsigned sh1(unsigned x, unsigned xm, unsigned xp) {
    return ((x << 1) | (xm >> 31)) | ((x >> 1) | (xp << 31));
}
__device__ __forceinline__ unsigned sh2(unsigned x, unsigned xm, unsigned xp) {
    return ((x << 2) | (xm >> 30)) | ((x >> 2) | (xp << 30));
}
__device__ __forceinline__ unsigned sh3(unsigned x, unsigned xm, unsigned xp) {
    return ((x << 3) | (xm >> 29)) | ((x >> 3) | (xp << 29));
}

// nearest set-bit horizontal distance in a 512-bit packed row (clamped 1024)
__device__ __forceinline__ int nearest_dj(const unsigned int* __restrict__ rb, int j) {
    int jw = j >> 5, jb = j & 31;
    unsigned wj = rb[jw];
    int dright = 1 << 20;
    unsigned hi = wj >> jb;
    if (hi) dright = __ffs(hi) - 1;
    else {
        #pragma unroll 4
        for (int w = jw + 1; w < 16; w++) {
            unsigned x = rb[w];
            if (x) { dright = (w << 5) + __ffs(x) - 1 - j; break; }
        }
    }
    int dleft = 1 << 20;
    unsigned lo = jb ? (wj & ((1u << jb) - 1u)) : 0u;
    if (lo) dleft = jb - (31 - __clz(lo));
    else {
        #pragma unroll 4
        for (int w = jw - 1; w >= 0; w--) {
            if ((j - ((w << 5) + 31)) >= dright) break;
            unsigned x = rb[w];
            if (x) { dleft = j - ((w << 5) + 31 - __clz(x)); break; }
        }
    }
    return min(min(dright, dleft), 1024);
}

// exact squared distance for a rare pixel with empty 7x7 (border corners etc.)
__device__ __noinline__ int exact_d2(int im, int row, int j) {
    int best2 = 1 << 19;
    for (int dr = 0; dr < HH; dr++) {
        int dr2 = dr * dr;
        if (dr2 >= best2) break;
        int r = row - dr;
        if (r >= 0) {
            int dj = nearest_dj(g_mbits[im][r], j);
            best2 = min(best2, dr2 + dj * dj);
        }
        if (dr) {
            r = row + dr;
            if (r < HH) {
                int dj = nearest_dj(g_mbits[im][r], j);
                best2 = min(best2, dr2 + dj * dj);
            }
        }
    }
    return best2;
}

// ======================= K1: pure streaming pack ============================
__global__ __launch_bounds__(K1THR)
void pack_kernel(const float* __restrict__ inA, const float* __restrict__ inB) {
    __shared__ __align__(8) unsigned char s_nib[K1THR / 32][128];
    const int t    = threadIdx.x;
    const int w    = t >> 5;
    const int lane = t & 31;
    const int u    = blockIdx.x * (K1THR / 32) + w;   // 0..4095
    const int im   = u >> 8;                          // 256 pairs per image
    const int row0 = (u & 255) * 2;
    const int half = lane >> 4;
    const int wj   = lane & 15;

    const float* src = ((im < NB) ? inA : inB) + (size_t)(im & 7) * HH * WW;
    const float4* r0 = (const float4*)(src + (size_t)row0 * WW);
    const float4* r1 = (const float4*)(src + (size_t)(row0 + 1) * WW);
    float4 a0 = r0[lane], a1 = r0[lane + 32], a2 = r0[lane + 64], a3 = r0[lane + 96];
    float4 b0 = r1[lane], b1 = r1[lane + 32], b2 = r1[lane + 64], b3 = r1[lane + 96];

    unsigned char* sn = &s_nib[w][0];
    sn[0 * 32 + lane] = (unsigned char)(nib4(a0) | (nib4(b0) << 4));
    sn[1 * 32 + lane] = (unsigned char)(nib4(a1) | (nib4(b1) << 4));
    sn[2 * 32 + lane] = (unsigned char)(nib4(a2) | (nib4(b2) << 4));
    sn[3 * 32 + lane] = (unsigned char)(nib4(a3) | (nib4(b3) << 4));
    __syncwarp();

    uint2 v = *(const uint2*)&sn[(wj >> 2) * 32 + (wj & 3) * 8];
    unsigned x = (v.x >> (4 * half)) & 0x0F0F0F0Fu;
    unsigned y = (v.y >> (4 * half)) & 0x0F0F0F0Fu;
    x = (x | (x >> 4)) & 0x00FF00FFu;  x = (x | (x >> 8)) & 0x0000FFFFu;
    y = (y | (y >> 4)) & 0x00FF00FFu;  y = (y | (y >> 8)) & 0x0000FFFFu;
    g_mbits[im][row0 + half][wj] = x | (y << 16);
}

// ======================= K2: tiers + reduce + finalize ======================
__global__ __launch_bounds__(K2THR)
void tier_kernel(float* __restrict__ out) {
    __shared__ int s_red[K2THR / 32];
    __shared__ unsigned s_old;
    const int t    = threadIdx.x;
    const int w    = t >> 5;
    const int lane = t & 31;
    const int blk  = blockIdx.x;
    const int u    = blk * (K2THR / 32) + w;   // 0..4095
    const int im   = u >> 8;
    const int row0 = (u & 255) * 2;
    const int half = lane >> 4;
    const int wj   = lane & 15;
    const int row  = row0 + half;
    const int oim  = im ^ 8;

    unsigned C  = g_mbits[im][row][wj];
    unsigned G  = g_mbits[oim][row][wj];
    unsigned peer = __shfl_xor_sync(FULL, C, 16);
    unsigned U1 = half ? peer : (row > 0 ? g_mbits[im][row - 1][wj] : 0u);
    unsigned D1 = half ? (row < HH - 1 ? g_mbits[im][row + 1][wj] : 0u) : peer;
    unsigned U2 = (row > 1)      ? g_mbits[im][row - 2][wj] : 0u;
    unsigned D2 = (row < HH - 2) ? g_mbits[im][row + 2][wj] : 0u;
    unsigned U3 = (row > 2)      ? g_mbits[im][row - 3][wj] : 0u;
    unsigned D3 = (row < HH - 3) ? g_mbits[im][row + 3][wj] : 0u;

    unsigned Cm  = __shfl_sync(FULL, C,  (lane + 31) & 31);
    unsigned Cp  = __shfl_sync(FULL, C,  (lane + 1) & 31);
    unsigned U1m = __shfl_sync(FULL, U1, (lane + 31) & 31);
    unsigned U1p = __shfl_sync(FULL, U1, (lane + 1) & 31);
    unsigned U2m = __shfl_sync(FULL, U2, (lane + 31) & 31);
    unsigned U2p = __shfl_sync(FULL, U2, (lane + 1) & 31);
    unsigned U3m = __shfl_sync(FULL, U3, (lane + 31) & 31);
    unsigned U3p = __shfl_sync(FULL, U3, (lane + 1) & 31);
    unsigned D1m = __shfl_sync(FULL, D1, (lane + 31) & 31);
    unsigned D1p = __shfl_sync(FULL, D1, (lane + 1) & 31);
    unsigned D2m = __shfl_sync(FULL, D2, (lane + 31) & 31);
    unsigned D2p = __shfl_sync(FULL, D2, (lane + 1) & 31);
    unsigned D3m = __shfl_sync(FULL, D3, (lane + 31) & 31);
    unsigned D3p = __shfl_sync(FULL, D3, (lane + 1) & 31);
    if (wj == 0)  { Cm = 0u; U1m = 0u; U2m = 0u; U3m = 0u; D1m = 0u; D2m = 0u; D3m = 0u; }
    if (wj == 15) { Cp = 0u; U1p = 0u; U2p = 0u; U3p = 0u; D1p = 0u; D2p = 0u; D3p = 0u; }

    unsigned t1  = sh1(C, Cm, Cp) | U1 | D1;
    unsigned t2  = sh1(U1, U1m, U1p) | sh1(D1, D1m, D1p);
    unsigned t4  = sh2(C, Cm, Cp) | U2 | D2;
    unsigned t5  = sh2(U1, U1m, U1p) | sh2(D1, D1m, D1p)
                 | sh1(U2, U2m, U2p) | sh1(D2, D2m, D2p);
    unsigned t8  = sh2(U2, U2m, U2p) | sh2(D2, D2m, D2p);
    unsigned t9  = sh3(C, Cm, Cp) | U3 | D3;
    unsigned t10 = sh3(U1, U1m, U1p) | sh3(D1, D1m, D1p)
                 | sh1(U3, U3m, U3p) | sh1(D3, D3m, D3p);
    unsigned t13 = sh3(U2, U2m, U2p) | sh3(D2, D2m, D2p)
                 | sh2(U3, U3m, U3p) | sh2(D3, D3m, D3p);
    unsigned t18 = sh3(U3, U3m, U3p) | sh3(D3, D3m, D3p);

    unsigned n = C;
    int v = 0;
    if (G & t1  & ~n) v = 1;  n |= t1;
    if (G & t2  & ~n) v = 2;  n |= t2;
    if (G & t4  & ~n) v = 4;  n |= t4;
    if (G & t5  & ~n) v = 5;  n |= t5;
    if (G & t8  & ~n) v = 8;  n |= t8;
    if (G & t9  & ~n) v = 9;  n |= t9;
    if (G & t10 & ~n) v = 10; n |= t10;
    if (G & t13 & ~n) v = 13; n |= t13;
    if (G & t18 & ~n) v = 18; n |= t18;

    unsigned leftover = G & ~n;           // only near borders, p <= 2^-16
    int j0 = wj * 32;
    while (leftover) {
        int b = __ffs(leftover) - 1;
        leftover &= leftover - 1u;
        v = max(v, exact_d2(im, row, j0 + b));   // g_mbits complete: kernel boundary
    }

    int anyb = __syncthreads_or(C != 0u);
    if (t == 0) g_anyp[im][(blk * (K2THR / 32) / 8) & 31] = anyb;  // 32 blocks/img

    #pragma unroll
    for (int o = 16; o > 0; o >>= 1)
        v = max(v, __shfl_down_sync(FULL, v, o));
    if (lane == 0) s_red[w] = v;
    __syncthreads();
    if (t == 0) {
        int m = s_red[0];
        #pragma unroll
        for (int k = 1; k < K2THR / 32; k++) m = max(m, s_red[k]);
        atomicMax(&g_hmax[im], (unsigned)m);
    }

    // last-arriving block finalizes
    __syncthreads();
    if (t == 0) {
        __threadfence();
        s_old = atomicAdd(&g_done, 1u);
    }
    __syncthreads();
    if (((s_old + 1u) % K2BLK) != 0u) return;

    if (t < 32) {
        float term = 0.0f;
        unsigned h2u = 0u;
        int aA = 0, aB = 0;
        if (t < NB) {
            h2u = max(g_hmax[t], g_hmax[t + 8]);
            #pragma unroll
            for (int k = 0; k < 32; k++) {
                aA |= g_anyp[t][k];
                aB |= g_anyp[t + 8][k];
            }
        }
        __syncwarp();
        if (t < NIMG) g_hmax[t] = 0u;        // reset for next replay
        if (t < NB) {
            bool empty = !(aA && aB);
            float hd = sqrtf((float)h2u);
            term = empty ? 1.0f : (1.0f - 1.0f / (1.0f + hd));
        }
        #pragma unroll
        for (int o = 16; o > 0; o >>= 1)
            term += __shfl_down_sync(FULL, term, o);
        if (t == 0) out[0] = term / (float)NB;
    }
}

extern "C" void kernel_launch(void* const* d_in, const int* in_sizes, int n_in,
                              void* d_out, int out_size) {
    const float* inputs  = (const float*)d_in[0];
    const float* targets = (const float*)d_in[1];
    float* out = (float*)d_out;
    pack_kernel<<<K1BLK, K1THR>>>(inputs, targets);
    tier_kernel<<<K2BLK, K2THR>>>(out);
}

// round 12
// speedup vs baseline: 1.0442x; 1.0442x over previous
#include <cuda_runtime.h>
#include <math.h>

#define HH 512
#define WW 512
#define NB 8
#define NIMG 16
#define NBLK 128          // <= 148 SMs: exactly ONE wave
#define NTHR 1024         // 32 warps per block
#define NWARP 32
#define PAIRBLK 16        // blocks per pair
#define FULL 0xffffffffu

// packed thresholded masks: [image][row][16 words of 32 cols] = 512 KB
__device__ unsigned int g_mbits[NIMG][HH][16];
// per-(image, sub-block) nonempty flags (overwritten every replay)
__device__ int g_anyp[NIMG][16];
// running max dt^2 per EDT-image; reset by finalizer each replay
__device__ unsigned int g_hmax[NIMG];
// monotonic per-pair barrier counters (padded to separate L2 lines) + done
__device__ unsigned int g_pairbar[NB * 32];
__device__ unsigned int g_done = 0;

__device__ __forceinline__ unsigned nib4(float4 v) {
    return (v.x > 0.5f ? 1u : 0u) | (v.y > 0.5f ? 2u : 0u)
         | (v.z > 0.5f ? 4u : 0u) | (v.w > 0.5f ? 8u : 0u);
}
__device__ __forceinline__ unsigned sh1(unsigned x, unsigned xm, unsigned xp) {
    return ((x << 1) | (xm >> 31)) | ((x >> 1) | (xp << 31));
}
__device__ __forceinline__ unsigned sh2(unsigned x, unsigned xm, unsigned xp) {
    return ((x << 2) | (xm >> 30)) | ((x >> 2) | (xp << 30));
}
__device__ __forceinline__ unsigned sh3(unsigned x, unsigned xm, unsigned xp) {
    return ((x << 3) | (xm >> 29)) | ((x >> 3) | (xp << 29));
}

// nearest set-bit horizontal distance in a 512-bit packed row (clamped 1024)
__device__ __forceinline__ int nearest_dj(const unsigned int* __restrict__ rb, int j) {
    int jw = j >> 5, jb = j & 31;
    unsigned wj = rb[jw];
    int dright = 1 << 20;
    unsigned hi = wj >> jb;
    if (hi) dright = __ffs(hi) - 1;
    else {
        #pragma unroll 4
        for (int w = jw + 1; w < 16; w++) {
            unsigned x = rb[w];
            if (x) { dright = (w << 5) + __ffs(x) - 1 - j; break; }
        }
    }
    int dleft = 1 << 20;
    unsigned lo = jb ? (wj & ((1u << jb) - 1u)) : 0u;
    if (lo) dleft = jb - (31 - __clz(lo));
    else {
        #pragma unroll 4
        for (int w = jw - 1; w >= 0; w--) {
            if ((j - ((w << 5) + 31)) >= dright) break;
            unsigned x = rb[w];
            if (x) { dleft = j - ((w << 5) + 31 - __clz(x)); break; }
        }
    }
    return min(min(dright, dleft), 1024);
}

// exact squared distance for a rare pixel with empty 7x7 (p <= 2^-16, borders)
__device__ __noinline__ int exact_d2(int im, int row, int j) {
    int best2 = 1 << 19;
    for (int dr = 0; dr < HH; dr++) {
        int dr2 = dr * dr;
        if (dr2 >= best2) break;
        int r = row - dr;
        if (r >= 0) {
            int dj = nearest_dj(g_mbits[im][r], j);
            best2 = min(best2, dr2 + dj * dj);
        }
        if (dr) {
            r = row + dr;
            if (r < HH) {
                int dj = nearest_dj(g_mbits[im][r], j);
                best2 = min(best2, dr2 + dj * dj);
            }
        }
    }
    return best2;
}

__global__ __launch_bounds__(NTHR, 1)
void hausdorff_fused(const float* __restrict__ inA,
                     const float* __restrict__ inB,
                     float* __restrict__ out) {
    __shared__ __align__(8) unsigned char s_nib[NWARP][128];
    __shared__ int s_red[NWARP];
    __shared__ int s_any[NWARP];
    __shared__ unsigned s_old;

    const int t    = threadIdx.x;
    const int w    = t >> 5;          // 0..31
    const int lane = t & 31;
    const int blk  = blockIdx.x;
    const int pr   = blk >> 4;        // pair 0..7
    const int sub  = blk & 15;        // sub-block within pair
    const int whi  = w >> 4;          // 0: A-image, 1: B-image
    const int wim  = w & 15;
    const int im   = pr + whi * 8;
    const int row0 = (sub * 16 + wim) * 2;
    const int half = lane >> 4;
    const int wj   = lane & 15;
    const int row  = row0 + half;

    unsigned C;
    // ------- Phase 1: coalesced threshold + bit-pack ------------------------
    {
        const float* src = (whi ? inB : inA) + (size_t)pr * HH * WW;
        const float4* r0 = (const float4*)(src + (size_t)row0 * WW);
        const float4* r1 = (const float4*)(src + (size_t)(row0 + 1) * WW);
        float4 a0 = r0[lane], a1 = r0[lane + 32], a2 = r0[lane + 64], a3 = r0[lane + 96];
        float4 b0 = r1[lane], b1 = r1[lane + 32], b2 = r1[lane + 64], b3 = r1[lane + 96];

        unsigned char* sn = &s_nib[w][0];
        sn[0 * 32 + lane] = (unsigned char)(nib4(a0) | (nib4(b0) << 4));
        sn[1 * 32 + lane] = (unsigned char)(nib4(a1) | (nib4(b1) << 4));
        sn[2 * 32 + lane] = (unsigned char)(nib4(a2) | (nib4(b2) << 4));
        sn[3 * 32 + lane] = (unsigned char)(nib4(a3) | (nib4(b3) << 4));
        __syncwarp();

        uint2 v = *(const uint2*)&sn[(wj >> 2) * 32 + (wj & 3) * 8];
        unsigned x = (v.x >> (4 * half)) & 0x0F0F0F0Fu;
        unsigned y = (v.y >> (4 * half)) & 0x0F0F0F0Fu;
        x = (x | (x >> 4)) & 0x00FF00FFu;  x = (x | (x >> 8)) & 0x0000FFFFu;
        y = (y | (y >> 4)) & 0x00FF00FFu;  y = (y | (y >> 8)) & 0x0000FFFFu;
        C = x | (y << 16);
        g_mbits[im][row][wj] = C;

        if (lane == 0) s_any[w] = 0;
        __syncwarp();
        if (__any_sync(FULL, C != 0u) && lane == 0) s_any[w] = 1;
    }

    // ------- per-pair barrier (16 co-resident blocks) -----------------------
    __threadfence();
    __syncthreads();
    if (t == 0) {
        int aA = 0, aB = 0;
        #pragma unroll
        for (int k = 0; k < 16; k++) { aA |= s_any[k]; aB |= s_any[k + 16]; }
        g_anyp[pr][sub]     = aA;
        g_anyp[pr + 8][sub] = aB;
        __threadfence();
        unsigned old = atomicAdd(&g_pairbar[pr * 32], 1u);
        unsigned target = (old / PAIRBLK + 1u) * PAIRBLK;
        while (*(volatile unsigned int*)&g_pairbar[pr * 32] < target) { }
        __threadfence();
    }
    __syncthreads();

    // ------- Phase 2: radius-3 tiered exact Hausdorff max -------------------
    {
        const int oim = im ^ 8;
        unsigned G  = g_mbits[oim][row][wj];
        unsigned peer = __shfl_xor_sync(FULL, C, 16);
        unsigned U1 = half ? peer : (row > 0 ? g_mbits[im][row - 1][wj] : 0u);
        unsigned D1 = half ? (row < HH - 1 ? g_mbits[im][row + 1][wj] : 0u) : peer;
        unsigned U2 = (row > 1)      ? g_mbits[im][row - 2][wj] : 0u;
        unsigned D2 = (row < HH - 2) ? g_mbits[im][row + 2][wj] : 0u;
        unsigned U3 = (row > 2)      ? g_mbits[im][row - 3][wj] : 0u;
        unsigned D3 = (row < HH - 3) ? g_mbits[im][row + 3][wj] : 0u;

        unsigned Cm  = __shfl_sync(FULL, C,  (lane + 31) & 31);
        unsigned Cp  = __shfl_sync(FULL, C,  (lane + 1) & 31);
        unsigned U1m = __shfl_sync(FULL, U1, (lane + 31) & 31);
        unsigned U1p = __shfl_sync(FULL, U1, (lane + 1) & 31);
        unsigned U2m = __shfl_sync(FULL, U2, (lane + 31) & 31);
        unsigned U2p = __shfl_sync(FULL, U2, (lane + 1) & 31);
        unsigned U3m = __shfl_sync(FULL, U3, (lane + 31) & 31);
        unsigned U3p = __shfl_sync(FULL, U3, (lane + 1) & 31);
        unsigned D1m = __shfl_sync(FULL, D1, (lane + 31) & 31);
        unsigned D1p = __shfl_sync(FULL, D1, (lane + 1) & 31);
        unsigned D2m = __shfl_sync(FULL, D2, (lane + 31) & 31);
        unsigned D2p = __shfl_sync(FULL, D2, (lane + 1) & 31);
        unsigned D3m = __shfl_sync(FULL, D3, (lane + 31) & 31);
        unsigned D3p = __shfl_sync(FULL, D3, (lane + 1) & 31);
        if (wj == 0)  { Cm = 0u; U1m = 0u; U2m = 0u; U3m = 0u; D1m = 0u; D2m = 0u; D3m = 0u; }
        if (wj == 15) { Cp = 0u; U1p = 0u; U2p = 0u; U3p = 0u; D1p = 0u; D2p = 0u; D3p = 0u; }

        unsigned t1  = sh1(C, Cm, Cp) | U1 | D1;
        unsigned t2  = sh1(U1, U1m, U1p) | sh1(D1, D1m, D1p);
        unsigned t4  = sh2(C, Cm, Cp) | U2 | D2;
        unsigned t5  = sh2(U1, U1m, U1p) | sh2(D1, D1m, D1p)
                     | sh1(U2, U2m, U2p) | sh1(D2, D2m, D2p);
        unsigned t8  = sh2(U2, U2m, U2p) | sh2(D2, D2m, D2p);
        unsigned t9  = sh3(C, Cm, Cp) | U3 | D3;
        unsigned t10 = sh3(U1, U1m, U1p) | sh3(D1, D1m, D1p)
                     | sh1(U3, U3m, U3p) | sh1(D3, D3m, D3p);
        unsigned t13 = sh3(U2, U2m, U2p) | sh3(D2, D2m, D2p)
                     | sh2(U3, U3m, U3p) | sh2(D3, D3m, D3p);
        unsigned t18 = sh3(U3, U3m, U3p) | sh3(D3, D3m, D3p);

        unsigned n = C;
        int v = 0;
        if (G & t1  & ~n) v = 1;  n |= t1;
        if (G & t2  & ~n) v = 2;  n |= t2;
        if (G & t4  & ~n) v = 4;  n |= t4;
        if (G & t5  & ~n) v = 5;  n |= t5;
        if (G & t8  & ~n) v = 8;  n |= t8;
        if (G & t9  & ~n) v = 9;  n |= t9;
        if (G & t10 & ~n) v = 10; n |= t10;
        if (G & t13 & ~n) v = 13; n |= t13;
        if (G & t18 & ~n) v = 18; n |= t18;

        unsigned leftover = G & ~n;
        int j0 = wj * 32;
        while (leftover) {
            int b = __ffs(leftover) - 1;
            leftover &= leftover - 1u;
            v = max(v, exact_d2(im, row, j0 + b));   // pair barrier guarantees g_mbits
        }

        #pragma unroll
        for (int o = 16; o > 0; o >>= 1)
            v = max(v, __shfl_down_sync(FULL, v, o));
        if (lane == 0) s_red[w] = v;
        __syncthreads();
        if (t == 0) {
            int mA = s_red[0], mB = s_red[16];
            #pragma unroll
            for (int k = 1; k < 16; k++) {
                mA = max(mA, s_red[k]);
                mB = max(mB, s_red[k + 16]);
            }
            atomicMax(&g_hmax[pr],     (unsigned)mA);
            atomicMax(&g_hmax[pr + 8], (unsigned)mB);
        }
    }

    // ------- completion: LAST-arriving block finalizes ----------------------
    __syncthreads();
    if (t == 0) {
        __threadfence();
        s_old = atomicAdd(&g_done, 1u);
    }
    __syncthreads();
    if (((s_old + 1u) % NBLK) != 0u) return;

    if (t < 32) {
        float term = 0.0f;
        unsigned h2u = 0u;
        int aA = 0, aB = 0;
        if (t < NB) {
            h2u = max(g_hmax[t], g_hmax[t + 8]);
            #pragma unroll
            for (int k = 0; k < 16; k++) {
                aA |= g_anyp[t][k];
                aB |= g_anyp[t + 8][k];
            }
        }
        __syncwarp();
        if (t < NIMG) g_hmax[t] = 0u;        // reset for next replay
        if (t < NB) {
            bool empty = !(aA && aB);
            float hd = sqrtf((float)h2u);
            term = empty ? 1.0f : (1.0f - 1.0f / (1.0f + hd));
        }
        #pragma unroll
        for (int o = 16; o > 0; o >>= 1)
            term += __shfl_down_sync(FULL, term, o);
        if (t == 0) out[0] = term / (float)NB;
    }
}

extern "C" void kernel_launch(void* const* d_in, const int* in_sizes, int n_in,
                              void* d_out, int out_size) {
    const float* inputs  = (const float*)d_in[0];
    const float* targets = (const float*)d_in[1];
    float* out = (float*)d_out;
    hausdorff_fused<<<NBLK, NTHR>>>(inputs, targets, out);
}

// round 13
// speedup vs baseline: 1.1420x; 1.0937x over previous
#include <cuda_runtime.h>
#include <math.h>

#define HH 512
#define WW 512
#define NB 8
#define NIMG 16
#define NBLK 128          // one wave
#define NTHR 1024
#define NWARP 32
#define FULL 0xffffffffu

__device__ unsigned int g_mbits[NIMG][HH][16];   // 512 KB, fallback path only
__device__ int g_anyp[NIMG][16];
__device__ unsigned int g_hmax[NIMG];
__device__ unsigned int g_ph1 = 0;               // monotonic pack-complete counter
__device__ unsigned int g_done = 0;              // monotonic finalize counter

__device__ __forceinline__ unsigned nib4(float4 v) {
    return (v.x > 0.5f ? 1u : 0u) | (v.y > 0.5f ? 2u : 0u)
         | (v.z > 0.5f ? 4u : 0u) | (v.w > 0.5f ? 8u : 0u);
}
__device__ __forceinline__ unsigned sh1(unsigned x, unsigned xm, unsigned xp) {
    return ((x << 1) | (xm >> 31)) | ((x >> 1) | (xp << 31));
}
__device__ __forceinline__ unsigned sh2(unsigned x, unsigned xm, unsigned xp) {
    return ((x << 2) | (xm >> 30)) | ((x >> 2) | (xp << 30));
}
__device__ __forceinline__ unsigned sh3(unsigned x, unsigned xm, unsigned xp) {
    return ((x << 3) | (xm >> 29)) | ((x >> 3) | (xp << 29));
}

__device__ __forceinline__ int nearest_dj(const unsigned int* __restrict__ rb, int j) {
    int jw = j >> 5, jb = j & 31;
    unsigned wj = rb[jw];
    int dright = 1 << 20;
    unsigned hi = wj >> jb;
    if (hi) dright = __ffs(hi) - 1;
    else {
        #pragma unroll 4
        for (int w = jw + 1; w < 16; w++) {
            unsigned x = rb[w];
            if (x) { dright = (w << 5) + __ffs(x) - 1 - j; break; }
        }
    }
    int dleft = 1 << 20;
    unsigned lo = jb ? (wj & ((1u << jb) - 1u)) : 0u;
    if (lo) dleft = jb - (31 - __clz(lo));
    else {
        #pragma unroll 4
        for (int w = jw - 1; w >= 0; w--) {
            if ((j - ((w << 5) + 31)) >= dright) break;
            unsigned x = rb[w];
            if (x) { dleft = j - ((w << 5) + 31 - __clz(x)); break; }
        }
    }
    return min(min(dright, dleft), 1024);
}

// exact d^2 for an ultra-rare pixel whose in-image 7x7 is empty
__device__ __noinline__ int exact_d2(int im, int row, int j) {
    int best2 = 1 << 19;
    for (int dr = 0; dr < HH; dr++) {
        int dr2 = dr * dr;
        if (dr2 >= best2) break;
        int r = row - dr;
        if (r >= 0) {
            int dj = nearest_dj(g_mbits[im][r], j);
            best2 = min(best2, dr2 + dj * dj);
        }
        if (dr) {
            r = row + dr;
            if (r < HH) {
                int dj = nearest_dj(g_mbits[im][r], j);
                best2 = min(best2, dr2 + dj * dj);
            }
        }
    }
    return best2;
}

// load row r of A (lanes' half 0) and row r of B (half 1), return this lane's word
__device__ __forceinline__ unsigned pack_unit(const float4* pA, const float4* pB,
                                              bool valid, unsigned char* sn,
                                              int lane, int half, int wj) {
    float4 z = make_float4(0.f, 0.f, 0.f, 0.f);
    float4 a0 = valid ? pA[lane] : z,      a1 = valid ? pA[lane + 32] : z;
    float4 a2 = valid ? pA[lane + 64] : z, a3 = valid ? pA[lane + 96] : z;
    float4 b0 = valid ? pB[lane] : z,      b1 = valid ? pB[lane + 32] : z;
    float4 b2 = valid ? pB[lane + 64] : z, b3 = valid ? pB[lane + 96] : z;
    sn[0 * 32 + lane] = (unsigned char)(nib4(a0) | (nib4(b0) << 4));
    sn[1 * 32 + lane] = (unsigned char)(nib4(a1) | (nib4(b1) << 4));
    sn[2 * 32 + lane] = (unsigned char)(nib4(a2) | (nib4(b2) << 4));
    sn[3 * 32 + lane] = (unsigned char)(nib4(a3) | (nib4(b3) << 4));
    __syncwarp();
    uint2 v = *(const uint2*)&sn[(wj >> 2) * 32 + (wj & 3) * 8];
    unsigned x = (v.x >> (4 * half)) & 0x0F0F0F0Fu;
    unsigned y = (v.y >> (4 * half)) & 0x0F0F0F0Fu;
    x = (x | (x >> 4)) & 0x00FF00FFu;  x = (x | (x >> 8)) & 0x0000FFFFu;
    y = (y | (y >> 4)) & 0x00FF00FFu;  y = (y | (y >> 8)) & 0x0000FFFFu;
    unsigned C = x | (y << 16);
    __syncwarp();                  // caller may reuse sn
    return C;
}

__global__ __launch_bounds__(NTHR, 1)
void hausdorff_fused(const float* __restrict__ inA,
                     const float* __restrict__ inB,
                     float* __restrict__ out) {
    __shared__ unsigned sA[38][17], sB[38][17];   // 32 central + 2*3 halo rows
    __shared__ __align__(8) unsigned char s_nib[NWARP][128];
    __shared__ int s_redA[NWARP], s_redB[NWARP], s_any[NWARP];
    __shared__ unsigned s_old, s_tgt;

    const int t    = threadIdx.x;
    const int w    = t >> 5;
    const int lane = t & 31;
    const int blk  = blockIdx.x;
    const int pr   = blk >> 4;          // pair 0..7
    const int seg  = blk & 15;          // 32-row segment
    const int r0   = seg * 32;
    const int half = lane >> 4;         // 0: image A, 1: image B
    const int wj   = lane & 15;
    const int row  = r0 + w;            // this warp's central row
    const int im   = pr + half * 8;

    const float* baseA = inA + (size_t)pr * HH * WW;
    const float* baseB = inB + (size_t)pr * HH * WW;

    // ---- Phase 1: central row (both images) + halo rows, pack to smem ------
    unsigned C = pack_unit((const float4*)(baseA + (size_t)row * WW),
                           (const float4*)(baseB + (size_t)row * WW),
                           true, &s_nib[w][0], lane, half, wj);
    if (half == 0) sA[3 + w][wj] = C; else sB[3 + w][wj] = C;
    g_mbits[im][row][wj] = C;

    if (w < 6) {                        // halo rows: 3 above, 3 below
        int hr = (w < 3) ? (r0 - 3 + w) : (r0 + 32 + (w - 3));
        int rl = (w < 3) ? w : (32 + w);     // 0..2 / 35..37
        bool valid = ((unsigned)hr < (unsigned)HH);
        const float4* hA = (const float4*)(baseA + (size_t)(valid ? hr : 0) * WW);
        const float4* hB = (const float4*)(baseB + (size_t)(valid ? hr : 0) * WW);
        unsigned Ch = pack_unit(hA, hB, valid, &s_nib[w][0], lane, half, wj);
        if (half == 0) sA[rl][wj] = Ch; else sB[rl][wj] = Ch;
    }

    {   // per-warp any flags (central rows only)
        unsigned bm = __ballot_sync(FULL, C != 0u);
        if (lane == 0) s_any[w] = (int)((bm & 0xFFFFu ? 1u : 0u) | (bm >> 16 ? 2u : 0u));
    }

    __syncthreads();
    if (t == 0) {       // publish pack-complete (for the ultra-rare exact path)
        __threadfence();
        unsigned old = atomicAdd(&g_ph1, 1u);
        s_tgt = (old / NBLK + 1u) * NBLK;
    }
    __syncthreads();

    // ---- Phase 2: tiers entirely from registers + shared memory ------------
    {
        const int rl = 3 + w;
        unsigned (*own)[17] = half ? sB : sA;
        unsigned (*oth)[17] = half ? sA : sB;
        unsigned G  = oth[rl][wj];
        unsigned U1 = own[rl - 1][wj], U2 = own[rl - 2][wj], U3 = own[rl - 3][wj];
        unsigned D1 = own[rl + 1][wj], D2 = own[rl + 2][wj], D3 = own[rl + 3][wj];

        unsigned Cm  = __shfl_sync(FULL, C,  (lane + 31) & 31);
        unsigned Cp  = __shfl_sync(FULL, C,  (lane + 1) & 31);
        unsigned U1m = __shfl_sync(FULL, U1, (lane + 31) & 31);
        unsigned U1p = __shfl_sync(FULL, U1, (lane + 1) & 31);
        unsigned U2m = __shfl_sync(FULL, U2, (lane + 31) & 31);
        unsigned U2p = __shfl_sync(FULL, U2, (lane + 1) & 31);
        unsigned U3m = __shfl_sync(FULL, U3, (lane + 31) & 31);
        unsigned U3p = __shfl_sync(FULL, U3, (lane + 1) & 31);
        unsigned D1m = __shfl_sync(FULL, D1, (lane + 31) & 31);
        unsigned D1p = __shfl_sync(FULL, D1, (lane + 1) & 31);
        unsigned D2m = __shfl_sync(FULL, D2, (lane + 31) & 31);
        unsigned D2p = __shfl_sync(FULL, D2, (lane + 1) & 31);
        unsigned D3m = __shfl_sync(FULL, D3, (lane + 31) & 31);
        unsigned D3p = __shfl_sync(FULL, D3, (lane + 1) & 31);
        if (wj == 0)  { Cm = 0u; U1m = 0u; U2m = 0u; U3m = 0u; D1m = 0u; D2m = 0u; D3m = 0u; }
        if (wj == 15) { Cp = 0u; U1p = 0u; U2p = 0u; U3p = 0u; D1p = 0u; D2p = 0u; D3p = 0u; }

        unsigned t1  = sh1(C, Cm, Cp) | U1 | D1;
        unsigned t2  = sh1(U1, U1m, U1p) | sh1(D1, D1m, D1p);
        unsigned t4  = sh2(C, Cm, Cp) | U2 | D2;
        unsigned t5  = sh2(U1, U1m, U1p) | sh2(D1, D1m, D1p)
                     | sh1(U2, U2m, U2p) | sh1(D2, D2m, D2p);
        unsigned t8  = sh2(U2, U2m, U2p) | sh2(D2, D2m, D2p);
        unsigned t9  = sh3(C, Cm, Cp) | U3 | D3;
        unsigned t10 = sh3(U1, U1m, U1p) | sh3(D1, D1m, D1p)
                     | sh1(U3, U3m, U3p) | sh1(D3, D3m, D3p);
        unsigned t13 = sh3(U2, U2m, U2p) | sh3(D2, D2m, D2p)
                     | sh2(U3, U3m, U3p) | sh2(D3, D3m, D3p);
        unsigned t18 = sh3(U3, U3m, U3p) | sh3(D3, D3m, D3p);

        unsigned n = C;
        int v = 0;
        if (G & t1  & ~n) v = 1;  n |= t1;
        if (G & t2  & ~n) v = 2;  n |= t2;
        if (G & t4  & ~n) v = 4;  n |= t4;
        if (G & t5  & ~n) v = 5;  n |= t5;
        if (G & t8  & ~n) v = 8;  n |= t8;
        if (G & t9  & ~n) v = 9;  n |= t9;
        if (G & t10 & ~n) v = 10; n |= t10;
        if (G & t13 & ~n) v = 13; n |= t13;
        if (G & t18 & ~n) v = 18; n |= t18;

        unsigned leftover = G & ~n;        // interior p ~ 2^-49; borders ~2^-16
        if (__any_sync(FULL, leftover != 0u)) {
            if (lane == 0)
                while (*(volatile unsigned int*)&g_ph1 < s_tgt) { }
            __syncwarp();
            __threadfence();
            int j0 = wj * 32;
            while (leftover) {
                int b = __ffs(leftover) - 1;
                leftover &= leftover - 1u;
                v = max(v, exact_d2(im, row, j0 + b));
            }
        }

        #pragma unroll
        for (int o = 8; o > 0; o >>= 1)
            v = max(v, __shfl_down_sync(FULL, v, o, 16));   // within 16-lane halves
        if (lane == 0)  s_redA[w] = v;
        if (lane == 16) s_redB[w] = v;
        __syncthreads();
        if (t == 0) {
            int mA = s_redA[0], mB = s_redB[0], aA = 0, aB = 0;
            #pragma unroll
            for (int k = 1; k < NWARP; k++) {
                mA = max(mA, s_redA[k]);
                mB = max(mB, s_redB[k]);
            }
            #pragma unroll
            for (int k = 0; k < NWARP; k++) { aA |= s_any[k] & 1; aB |= s_any[k] & 2; }
            g_anyp[pr][seg]     = aA ? 1 : 0;
            g_anyp[pr + 8][seg] = aB ? 1 : 0;
            atomicMax(&g_hmax[pr],     (unsigned)mA);
            atomicMax(&g_hmax[pr + 8], (unsigned)mB);
        }
    }

    // ---- completion: LAST-arriving block finalizes -------------------------
    __syncthreads();
    if (t == 0) {
        __threadfence();
        s_old = atomicAdd(&g_done, 1u);
    }
    __syncthreads();
    if (((s_old + 1u) % NBLK) != 0u) return;

    if (t < 32) {
        float term = 0.0f;
        unsigned h2u = 0u;
        int aA = 0, aB = 0;
        if (t < NB) {
            h2u = max(g_hmax[t], g_hmax[t + 8]);
            #pragma unroll
            for (int k = 0; k < 16; k++) {
                aA |= g_anyp[t][k];
                aB |= g_anyp[t + 8][k];
            }
        }
        __syncwarp();
        if (t < NIMG) g_hmax[t] = 0u;        // reset for next replay
        if (t < NB) {
            bool empty = !(aA && aB);
            float hd = sqrtf((float)h2u);
            term = empty ? 1.0f : (1.0f - 1.0f / (1.0f + hd));
        }
        #pragma unroll
        for (int o = 16; o > 0; o >>= 1)
            term += __shfl_down_sync(FULL, term, o);
        if (t == 0) out[0] = term / (float)NB;
    }
}

extern "C" void kernel_launch(void* const* d_in, const int* in_sizes, int n_in,
                              void* d_out, int out_size) {
    const float* inputs  = (const float*)d_in[0];
    const float* targets = (const float*)d_in[1];
    float* out = (float*)d_out;
    hausdorff_fused<<<NBLK, NTHR>>>(inputs, targets, out);
}

// round 14
// speedup vs baseline: 1.1585x; 1.0144x over previous
#include <cuda_runtime.h>
#include <math.h>

#define HH 512
#define WW 512
#define NB 8
#define NIMG 16
#define NBLK 128          // one wave
#define NTHR 1024
#define NWARP 32
#define FULL 0xffffffffu

__device__ unsigned int g_mbits[NIMG][HH][16];   // 512 KB, fallback path only
__device__ unsigned int g_anybits;               // bit im: mask nonempty (idempotent OR)
__device__ unsigned int g_hmax[NIMG];
__device__ unsigned int g_ph1 = 0;               // monotonic pack-complete counter
__device__ unsigned int g_done = 0;              // monotonic finalize counter

__device__ __forceinline__ unsigned nib4(float4 v) {
    return (v.x > 0.5f ? 1u : 0u) | (v.y > 0.5f ? 2u : 0u)
         | (v.z > 0.5f ? 4u : 0u) | (v.w > 0.5f ? 8u : 0u);
}

__device__ __forceinline__ int nearest_dj(const unsigned int* __restrict__ rb, int j) {
    int jw = j >> 5, jb = j & 31;
    unsigned wj = rb[jw];
    int dright = 1 << 20;
    unsigned hi = wj >> jb;
    if (hi) dright = __ffs(hi) - 1;
    else {
        #pragma unroll 4
        for (int w = jw + 1; w < 16; w++) {
            unsigned x = rb[w];
            if (x) { dright = (w << 5) + __ffs(x) - 1 - j; break; }
        }
    }
    int dleft = 1 << 20;
    unsigned lo = jb ? (wj & ((1u << jb) - 1u)) : 0u;
    if (lo) dleft = jb - (31 - __clz(lo));
    else {
        #pragma unroll 4
        for (int w = jw - 1; w >= 0; w--) {
            if ((j - ((w << 5) + 31)) >= dright) break;
            unsigned x = rb[w];
            if (x) { dleft = j - ((w << 5) + 31 - __clz(x)); break; }
        }
    }
    return min(min(dright, dleft), 1024);
}

// exact d^2 for an ultra-rare pixel whose in-image 7x7 is empty
__device__ __noinline__ int exact_d2(int im, int row, int j) {
    int best2 = 1 << 19;
    for (int dr = 0; dr < HH; dr++) {
        int dr2 = dr * dr;
        if (dr2 >= best2) break;
        int r = row - dr;
        if (r >= 0) {
            int dj = nearest_dj(g_mbits[im][r], j);
            best2 = min(best2, dr2 + dj * dj);
        }
        if (dr) {
            r = row + dr;
            if (r < HH) {
                int dj = nearest_dj(g_mbits[im][r], j);
                best2 = min(best2, dr2 + dj * dj);
            }
        }
    }
    return best2;
}

__device__ __forceinline__ unsigned assemble(const unsigned char* sn, int half, int wj) {
    uint2 v = *(const uint2*)&sn[(wj >> 2) * 32 + (wj & 3) * 8];
    unsigned x = (v.x >> (4 * half)) & 0x0F0F0F0Fu;
    unsigned y = (v.y >> (4 * half)) & 0x0F0F0F0Fu;
    x = (x | (x >> 4)) & 0x00FF00FFu;  x = (x | (x >> 8)) & 0x0000FFFFu;
    y = (y | (y >> 4)) & 0x00FF00FFu;  y = (y | (y >> 8)) & 0x0000FFFFu;
    return x | (y << 16);
}

// smear by N with cross-word carries (single funnel shifts)
#define SMEAR(x, xm, xp, N) (__funnelshift_l((xm), (x), (N)) | __funnelshift_r((x), (xp), (N)))

__global__ __launch_bounds__(NTHR, 1)
void hausdorff_fused(const float* __restrict__ inA,
                     const float* __restrict__ inB,
                     float* __restrict__ out) {
    __shared__ unsigned sA[38][17], sB[38][17];
    __shared__ __align__(8) unsigned char s_nib[NWARP][128];
    __shared__ __align__(8) unsigned char s_nib2[6][128];
    __shared__ int s_redA[NWARP], s_redB[NWARP];
    __shared__ unsigned s_any[NWARP];
    __shared__ unsigned s_old, s_tgt;

    const int t    = threadIdx.x;
    const int w    = t >> 5;
    const int lane = t & 31;
    const int blk  = blockIdx.x;
    const int pr   = blk >> 4;
    const int seg  = blk & 15;
    const int r0   = seg * 32;
    const int half = lane >> 4;         // 0: image A, 1: image B
    const int wj   = lane & 15;
    const int row  = r0 + w;
    const int im   = pr + half * 8;

    const float* baseA = inA + (size_t)pr * HH * WW;
    const float* baseB = inB + (size_t)pr * HH * WW;

    // ---- Phase 1: loads first (central + halo issued together), then pack --
    const float4* pA = (const float4*)(baseA + (size_t)row * WW);
    const float4* pB = (const float4*)(baseB + (size_t)row * WW);
    float4 ca0 = pA[lane], ca1 = pA[lane + 32], ca2 = pA[lane + 64], ca3 = pA[lane + 96];
    float4 cb0 = pB[lane], cb1 = pB[lane + 32], cb2 = pB[lane + 64], cb3 = pB[lane + 96];

    int hrl = 0; bool isHalo = (w < 6);
    float4 ha0, ha1, ha2, ha3, hb0, hb1, hb2, hb3;
    if (isHalo) {
        int hr = (w < 3) ? (r0 - 3 + w) : (r0 + 32 + (w - 3));
        hrl = (w < 3) ? w : (32 + w);          // 0..2 / 35..37
        bool valid = ((unsigned)hr < (unsigned)HH);
        float4 z = make_float4(0.f, 0.f, 0.f, 0.f);
        const float4* hA = (const float4*)(baseA + (size_t)(valid ? hr : 0) * WW);
        const float4* hB = (const float4*)(baseB + (size_t)(valid ? hr : 0) * WW);
        ha0 = valid ? hA[lane] : z;      ha1 = valid ? hA[lane + 32] : z;
        ha2 = valid ? hA[lane + 64] : z; ha3 = valid ? hA[lane + 96] : z;
        hb0 = valid ? hB[lane] : z;      hb1 = valid ? hB[lane + 32] : z;
        hb2 = valid ? hB[lane + 64] : z; hb3 = valid ? hB[lane + 96] : z;
    }

    unsigned char* sn = &s_nib[w][0];
    sn[0 * 32 + lane] = (unsigned char)(nib4(ca0) | (nib4(cb0) << 4));
    sn[1 * 32 + lane] = (unsigned char)(nib4(ca1) | (nib4(cb1) << 4));
    sn[2 * 32 + lane] = (unsigned char)(nib4(ca2) | (nib4(cb2) << 4));
    sn[3 * 32 + lane] = (unsigned char)(nib4(ca3) | (nib4(cb3) << 4));
    if (isHalo) {
        unsigned char* s2 = &s_nib2[w][0];
        s2[0 * 32 + lane] = (unsigned char)(nib4(ha0) | (nib4(hb0) << 4));
        s2[1 * 32 + lane] = (unsigned char)(nib4(ha1) | (nib4(hb1) << 4));
        s2[2 * 32 + lane] = (unsigned char)(nib4(ha2) | (nib4(hb2) << 4));
        s2[3 * 32 + lane] = (unsigned char)(nib4(ha3) | (nib4(hb3) << 4));
    }
    __syncwarp();

    unsigned C = assemble(&s_nib[w][0], half, wj);
    if (half == 0) sA[3 + w][wj] = C; else sB[3 + w][wj] = C;
    g_mbits[im][row][wj] = C;
    if (isHalo) {
        unsigned Ch = assemble(&s_nib2[w][0], half, wj);
        if (half == 0) sA[hrl][wj] = Ch; else sB[hrl][wj] = Ch;
    }

    {
        unsigned bm = __ballot_sync(FULL, C != 0u);
        if (lane == 0)
            s_any[w] = (bm & 0xFFFFu ? 1u : 0u) | ((bm >> 16) ? 2u : 0u);
    }

    __syncthreads();
    if (t == 0) {          // publish pack-complete (for the ultra-rare exact path)
        __threadfence();
        unsigned old = atomicAdd(&g_ph1, 1u);
        s_tgt = (old / NBLK + 1u) * NBLK;
    }

    // ---- Phase 2: V-factorized radius-3 tiers from smem --------------------
    int v = 0;
    {
        const int rl = 3 + w;
        unsigned (*own)[17] = half ? sB : sA;
        unsigned (*oth)[17] = half ? sA : sB;
        unsigned G  = oth[rl][wj];
        unsigned V1 = own[rl - 1][wj] | own[rl + 1][wj];
        unsigned V2 = own[rl - 2][wj] | own[rl + 2][wj];
        unsigned V3 = own[rl - 3][wj] | own[rl + 3][wj];

        unsigned Cm  = __shfl_sync(FULL, C,  (lane + 31) & 31);
        unsigned Cp  = __shfl_sync(FULL, C,  (lane + 1) & 31);
        unsigned V1m = __shfl_sync(FULL, V1, (lane + 31) & 31);
        unsigned V1p = __shfl_sync(FULL, V1, (lane + 1) & 31);
        unsigned V2m = __shfl_sync(FULL, V2, (lane + 31) & 31);
        unsigned V2p = __shfl_sync(FULL, V2, (lane + 1) & 31);
        unsigned V3m = __shfl_sync(FULL, V3, (lane + 31) & 31);
        unsigned V3p = __shfl_sync(FULL, V3, (lane + 1) & 31);
        if (wj == 0)  { Cm = 0u; V1m = 0u; V2m = 0u; V3m = 0u; }
        if (wj == 15) { Cp = 0u; V1p = 0u; V2p = 0u; V3p = 0u; }

        unsigned t1  = SMEAR(C, Cm, Cp, 1) | V1;
        unsigned t2  = SMEAR(V1, V1m, V1p, 1);
        unsigned t4  = SMEAR(C, Cm, Cp, 2) | V2;
        unsigned t5  = SMEAR(V1, V1m, V1p, 2) | SMEAR(V2, V2m, V2p, 1);
        unsigned t8  = SMEAR(V2, V2m, V2p, 2);
        unsigned t9  = SMEAR(C, Cm, Cp, 3) | V3;
        unsigned t10 = SMEAR(V1, V1m, V1p, 3) | SMEAR(V3, V3m, V3p, 1);
        unsigned t13 = SMEAR(V2, V2m, V2p, 3) | SMEAR(V3, V3m, V3p, 2);
        unsigned t18 = SMEAR(V3, V3m, V3p, 3);

        unsigned n = C;
        if (G & t1  & ~n) v = 1;  n |= t1;
        if (G & t2  & ~n) v = 2;  n |= t2;
        if (G & t4  & ~n) v = 4;  n |= t4;
        if (G & t5  & ~n) v = 5;  n |= t5;
        if (G & t8  & ~n) v = 8;  n |= t8;
        if (G & t9  & ~n) v = 9;  n |= t9;
        if (G & t10 & ~n) v = 10; n |= t10;
        if (G & t13 & ~n) v = 13; n |= t13;
        if (G & t18 & ~n) v = 18; n |= t18;

        unsigned leftover = G & ~n;        // interior p ~ 2^-49; borders ~2^-16
        if (__any_sync(FULL, leftover != 0u)) {
            __syncwarp();
            if (lane == 0)
                while (*(volatile unsigned int*)&g_ph1 < s_tgt) { }
            __syncwarp();
            __threadfence();
            int j0 = wj * 32;
            while (leftover) {
                int b = __ffs(leftover) - 1;
                leftover &= leftover - 1u;
                v = max(v, exact_d2(im, row, j0 + b));
            }
        }

        #pragma unroll
        for (int o = 8; o > 0; o >>= 1)
            v = max(v, __shfl_down_sync(FULL, v, o, 16));   // within 16-lane halves
        if (lane == 0)  s_redA[w] = v;
        if (lane == 16) s_redB[w] = v;
    }
    __syncthreads();

    // ---- block combine: warp 0, fully parallel -----------------------------
    if (w == 0) {
        int vA = s_redA[lane], vB = s_redB[lane];
        unsigned ab = s_any[lane];
        #pragma unroll
        for (int o = 16; o > 0; o >>= 1) {
            vA = max(vA, __shfl_down_sync(FULL, vA, o));
            vB = max(vB, __shfl_down_sync(FULL, vB, o));
            ab |= __shfl_down_sync(FULL, ab, o);
        }
        if (lane == 0) {
            atomicMax(&g_hmax[pr],     (unsigned)vA);
            atomicMax(&g_hmax[pr + 8], (unsigned)vB);
            unsigned bits = ((ab & 1u) ? (1u << pr) : 0u)
                          | ((ab & 2u) ? (1u << (pr + 8)) : 0u);
            if (bits) atomicOr(&g_anybits, bits);   // idempotent across replays
        }
    }

    // ---- completion: LAST-arriving block finalizes -------------------------
    __syncthreads();
    if (t == 0) {
        __threadfence();
        s_old = atomicAdd(&g_done, 1u);
    }
    __syncthreads();
    if (((s_old + 1u) % NBLK) != 0u) return;

    if (t < 32) {
        float term = 0.0f;
        unsigned h2u = 0u;
        unsigned ab = g_anybits;
        if (t < NB) h2u = max(g_hmax[t], g_hmax[t + 8]);
        __syncwarp();
        if (t < NIMG) g_hmax[t] = 0u;        // harmless (max is idempotent anyway)
        if (t < NB) {
            bool empty = !(((ab >> t) & 1u) && ((ab >> (t + 8)) & 1u));
            float hd = sqrtf((float)h2u);
            term = empty ? 1.0f : (1.0f - 1.0f / (1.0f + hd));
        }
        #pragma unroll
        for (int o = 16; o > 0; o >>= 1)
            term += __shfl_down_sync(FULL, term, o);
        if (t == 0) out[0] = term / (float)NB;
    }
}

extern "C" void kernel_launch(void* const* d_in, const int* in_sizes, int n_in,
                              void* d_out, int out_size) {
    const float* inputs  = (const float*)d_in[0];
    const float* targets = (const float*)d_in[1];
    float* out = (float*)d_out;
    hausdorff_fused<<<NBLK, NTHR>>>(inputs, targets, out);
}

// round 15
// speedup vs baseline: 1.2036x; 1.0389x over previous
#include <cuda_runtime.h>
#include <math.h>

#define HH 512
#define WW 512
#define NB 8
#define NIMG 16
#define NBLK 128          // 8 pairs x 16 segments: one wave
#define NTHR 1024
#define NWARP 32
#define FULL 0xffffffffu

__device__ unsigned int g_mbits[NIMG][HH][16];   // 512 KB: border context + fallback
__device__ unsigned int g_anybits;               // bit im: nonempty (idempotent OR)
__device__ unsigned int g_hmax[NIMG];
__device__ unsigned int g_segflag[NBLK];         // monotonic per-block publish flags
__device__ unsigned int g_ph1 = 0;               // monotonic pack-complete counter
__device__ unsigned int g_done = 0;              // monotonic finalize counter

__device__ __forceinline__ unsigned nib4(float4 v) {
    return (v.x > 0.5f ? 1u : 0u) | (v.y > 0.5f ? 2u : 0u)
         | (v.z > 0.5f ? 4u : 0u) | (v.w > 0.5f ? 8u : 0u);
}

__device__ __forceinline__ int nearest_dj(const unsigned int* __restrict__ rb, int j) {
    int jw = j >> 5, jb = j & 31;
    unsigned wj = rb[jw];
    int dright = 1 << 20;
    unsigned hi = wj >> jb;
    if (hi) dright = __ffs(hi) - 1;
    else {
        #pragma unroll 4
        for (int w = jw + 1; w < 16; w++) {
            unsigned x = rb[w];
            if (x) { dright = (w << 5) + __ffs(x) - 1 - j; break; }
        }
    }
    int dleft = 1 << 20;
    unsigned lo = jb ? (wj & ((1u << jb) - 1u)) : 0u;
    if (lo) dleft = jb - (31 - __clz(lo));
    else {
        #pragma unroll 4
        for (int w = jw - 1; w >= 0; w--) {
            if ((j - ((w << 5) + 31)) >= dright) break;
            unsigned x = rb[w];
            if (x) { dleft = j - ((w << 5) + 31 - __clz(x)); break; }
        }
    }
    return min(min(dright, dleft), 1024);
}

// exact d^2 for an ultra-rare pixel whose in-image 7x7 is empty
__device__ __noinline__ int exact_d2(int im, int row, int j) {
    int best2 = 1 << 19;
    for (int dr = 0; dr < HH; dr++) {
        int dr2 = dr * dr;
        if (dr2 >= best2) break;
        int r = row - dr;
        if (r >= 0) {
            int dj = nearest_dj(g_mbits[im][r], j);
            best2 = min(best2, dr2 + dj * dj);
        }
        if (dr) {
            r = row + dr;
            if (r < HH) {
                int dj = nearest_dj(g_mbits[im][r], j);
                best2 = min(best2, dr2 + dj * dj);
            }
        }
    }
    return best2;
}

__device__ __forceinline__ unsigned assemble(const unsigned char* sn, int half, int wj) {
    uint2 v = *(const uint2*)&sn[(wj >> 2) * 32 + (wj & 3) * 8];
    unsigned x = (v.x >> (4 * half)) & 0x0F0F0F0Fu;
    unsigned y = (v.y >> (4 * half)) & 0x0F0F0F0Fu;
    x = (x | (x >> 4)) & 0x00FF00FFu;  x = (x | (x >> 8)) & 0x0000FFFFu;
    y = (y | (y >> 4)) & 0x00FF00FFu;  y = (y | (y >> 8)) & 0x0000FFFFu;
    return x | (y << 16);
}

#define SMEAR(x, xm, xp, N) (__funnelshift_l((xm), (x), (N)) | __funnelshift_r((x), (xp), (N)))

__global__ __launch_bounds__(NTHR, 1)
void hausdorff_fused(const float* __restrict__ inA,
                     const float* __restrict__ inB,
                     float* __restrict__ out) {
    __shared__ unsigned sA[32][17], sB[32][17];
    __shared__ __align__(8) unsigned char s_nib[NWARP][128];
    __shared__ int s_redA[NWARP], s_redB[NWARP];
    __shared__ unsigned s_any[NWARP];
    __shared__ unsigned s_old, s_tgt, s_gen;

    const int t    = threadIdx.x;
    const int w    = t >> 5;
    const int lane = t & 31;
    const int blk  = blockIdx.x;
    const int pr   = blk >> 4;          // pair 0..7
    const int seg  = blk & 15;          // 32-row segment
    const int r0   = seg * 32;
    const int half = lane >> 4;         // 0: image A, 1: image B
    const int wj   = lane & 15;
    const int row  = r0 + w;
    const int im   = pr + half * 8;

    if (t == 0) s_gen = g_segflag[blk];   // own flag: stable this replay

    // ---- Phase 1: every warp loads exactly one row of both images ----------
    const float* baseA = inA + (size_t)pr * HH * WW;
    const float* baseB = inB + (size_t)pr * HH * WW;
    const float4* pA = (const float4*)(baseA + (size_t)row * WW);
    const float4* pB = (const float4*)(baseB + (size_t)row * WW);
    float4 a0 = pA[lane], a1 = pA[lane + 32], a2 = pA[lane + 64], a3 = pA[lane + 96];
    float4 b0 = pB[lane], b1 = pB[lane + 32], b2 = pB[lane + 64], b3 = pB[lane + 96];

    unsigned char* sn = &s_nib[w][0];
    sn[0 * 32 + lane] = (unsigned char)(nib4(a0) | (nib4(b0) << 4));
    sn[1 * 32 + lane] = (unsigned char)(nib4(a1) | (nib4(b1) << 4));
    sn[2 * 32 + lane] = (unsigned char)(nib4(a2) | (nib4(b2) << 4));
    sn[3 * 32 + lane] = (unsigned char)(nib4(a3) | (nib4(b3) << 4));
    __syncwarp();

    unsigned C = assemble(sn, half, wj);
    if (half == 0) sA[w][wj] = C; else sB[w][wj] = C;
    g_mbits[im][row][wj] = C;

    {
        unsigned bm = __ballot_sync(FULL, C != 0u);
        if (lane == 0)
            s_any[w] = (bm & 0xFFFFu ? 1u : 0u) | ((bm >> 16) ? 2u : 0u);
    }

    // border warps' rows are read remotely -> make them globally visible
    if (w < 3 || w > 28) __threadfence();
    __syncthreads();
    if (t == 0) {
        unsigned old = atomicAdd(&g_ph1, 1u);      // global pack count (fallback)
        s_tgt = (old / NBLK + 1u) * NBLK;
        atomicAdd(&g_segflag[blk], 1u);            // publish to neighbors
    }

    // ---- Phase 2: V-factorized radius-3 tiers ------------------------------
    int v = 0;
    {
        unsigned (*own)[17] = half ? sB : sA;
        unsigned (*oth)[17] = half ? sA : sB;
        unsigned G = oth[w][wj];

        // neighbor wait (6 warps max; single-wave residency -> no deadlock)
        bool needUp = (w < 3)  && (seg > 0);
        bool needDn = (w > 28) && (seg < 15);
        if (needUp || needDn) {
            int nb = needUp ? (blk - 1) : (blk + 1);
            if (lane == 0) {
                unsigned tgt = s_gen + 1u;
                while (*(volatile unsigned int*)&g_segflag[nb] < tgt) { }
            }
            __syncwarp();
            __threadfence();
        }

        unsigned U[3], D[3];
        #pragma unroll
        for (int k = 1; k <= 3; k++) {
            int lu = w - k;
            U[k - 1] = (lu >= 0) ? own[lu][wj]
                     : ((row - k >= 0) ? g_mbits[im][row - k][wj] : 0u);
            int ld = w + k;
            D[k - 1] = (ld <= 31) ? own[ld][wj]
                     : ((row + k < HH) ? g_mbits[im][row + k][wj] : 0u);
        }
        unsigned V1 = U[0] | D[0], V2 = U[1] | D[1], V3 = U[2] | D[2];

        unsigned Cm  = __shfl_sync(FULL, C,  (lane + 31) & 31);
        unsigned Cp  = __shfl_sync(FULL, C,  (lane + 1) & 31);
        unsigned V1m = __shfl_sync(FULL, V1, (lane + 31) & 31);
        unsigned V1p = __shfl_sync(FULL, V1, (lane + 1) & 31);
        unsigned V2m = __shfl_sync(FULL, V2, (lane + 31) & 31);
        unsigned V2p = __shfl_sync(FULL, V2, (lane + 1) & 31);
        unsigned V3m = __shfl_sync(FULL, V3, (lane + 31) & 31);
        unsigned V3p = __shfl_sync(FULL, V3, (lane + 1) & 31);
        if (wj == 0)  { Cm = 0u; V1m = 0u; V2m = 0u; V3m = 0u; }
        if (wj == 15) { Cp = 0u; V1p = 0u; V2p = 0u; V3p = 0u; }

        unsigned t1  = SMEAR(C, Cm, Cp, 1) | V1;
        unsigned t2  = SMEAR(V1, V1m, V1p, 1);
        unsigned t4  = SMEAR(C, Cm, Cp, 2) | V2;
        unsigned t5  = SMEAR(V1, V1m, V1p, 2) | SMEAR(V2, V2m, V2p, 1);
        unsigned t8  = SMEAR(V2, V2m, V2p, 2);
        unsigned t9  = SMEAR(C, Cm, Cp, 3) | V3;
        unsigned t10 = SMEAR(V1, V1m, V1p, 3) | SMEAR(V3, V3m, V3p, 1);
        unsigned t13 = SMEAR(V2, V2m, V2p, 3) | SMEAR(V3, V3m, V3p, 2);
        unsigned t18 = SMEAR(V3, V3m, V3p, 3);

        unsigned n = C;
        if (G & t1  & ~n) v = 1;  n |= t1;
        if (G & t2  & ~n) v = 2;  n |= t2;
        if (G & t4  & ~n) v = 4;  n |= t4;
        if (G & t5  & ~n) v = 5;  n |= t5;
        if (G & t8  & ~n) v = 8;  n |= t8;
        if (G & t9  & ~n) v = 9;  n |= t9;
        if (G & t10 & ~n) v = 10; n |= t10;
        if (G & t13 & ~n) v = 13; n |= t13;
        if (G & t18 & ~n) v = 18; n |= t18;

        unsigned leftover = G & ~n;        // interior p ~ 2^-49; borders ~2^-16
        if (__any_sync(FULL, leftover != 0u)) {
            if (lane == 0)
                while (*(volatile unsigned int*)&g_ph1 < s_tgt) { }
            __syncwarp();
            __threadfence();
            int j0 = wj * 32;
            while (leftover) {
                int b = __ffs(leftover) - 1;
                leftover &= leftover - 1u;
                v = max(v, exact_d2(im, row, j0 + b));
            }
        }

        #pragma unroll
        for (int o = 8; o > 0; o >>= 1)
            v = max(v, __shfl_down_sync(FULL, v, o, 16));
        if (lane == 0)  s_redA[w] = v;
        if (lane == 16) s_redB[w] = v;
    }
    __syncthreads();

    // ---- block combine: warp 0, fully parallel -----------------------------
    if (w == 0) {
        int vA = s_redA[lane], vB = s_redB[lane];
        unsigned ab = s_any[lane];
        #pragma unroll
        for (int o = 16; o > 0; o >>= 1) {
            vA = max(vA, __shfl_down_sync(FULL, vA, o));
            vB = max(vB, __shfl_down_sync(FULL, vB, o));
            ab |= __shfl_down_sync(FULL, ab, o);
        }
        if (lane == 0) {
            atomicMax(&g_hmax[pr],     (unsigned)vA);
            atomicMax(&g_hmax[pr + 8], (unsigned)vB);
            unsigned bits = ((ab & 1u) ? (1u << pr) : 0u)
                          | ((ab & 2u) ? (1u << (pr + 8)) : 0u);
            if (bits) atomicOr(&g_anybits, bits);
        }
    }

    // ---- completion: LAST-arriving block finalizes -------------------------
    __syncthreads();
    if (t == 0) {
        __threadfence();
        s_old = atomicAdd(&g_done, 1u);
    }
    __syncthreads();
    if (((s_old + 1u) % NBLK) != 0u) return;

    if (t < 32) {
        float term = 0.0f;
        unsigned h2u = 0u;
        unsigned ab = g_anybits;
        if (t < NB) h2u = max(g_hmax[t], g_hmax[t + 8]);
        __syncwarp();
        if (t < NIMG) g_hmax[t] = 0u;        // reset for next replay
        if (t < NB) {
            bool empty = !(((ab >> t) & 1u) && ((ab >> (t + 8)) & 1u));
            float hd = sqrtf((float)h2u);
            term = empty ? 1.0f : (1.0f - 1.0f / (1.0f + hd));
        }
        #pragma unroll
        for (int o = 16; o > 0; o >>= 1)
            term += __shfl_down_sync(FULL, term, o);
        if (t == 0) out[0] = term / (float)NB;
    }
}

extern "C" void kernel_launch(void* const* d_in, const int* in_sizes, int n_in,
                              void* d_out, int out_size) {
    const float* inputs  = (const float*)d_in[0];
    const float* targets = (const float*)d_in[1];
    float* out = (float*)d_out;
    hausdorff_fused<<<NBLK, NTHR>>>(inputs, targets, out);
}